// round 15
// baseline (speedup 1.0000x reference)
#include <cuda_runtime.h>
#include <cuda_fp16.h>
#include <cstdint>
#include <cstddef>

// ---------------- problem constants ----------------
#define NN   100000
#define EE   1600000
#define ELL  (EE+NN)
#define CH   128
#define BG   512
#define NHID 512
#define NOUT 256
#define NB_SCAN 98   // ceil(NN/1024)

// ---------------- scratch (__device__ globals; no allocs allowed) ----------------
__device__ __align__(16) __half g_h16[(size_t)NN*CH];
__device__ __align__(16) float g_agg[(size_t)NN*CH];
__device__ __align__(16) float g_x  [(size_t)NN*CH];
__device__ int   g_deg[NN];
__device__ float g_dinv[NN];
__device__ int   g_rowptr[NN+1];
__device__ int   g_cur[NN];
__device__ int   g_col[ELL];
__device__ float g_enorm[ELL];
__device__ float g_es[NN];
__device__ float g_ed[NN];
__device__ __align__(16) float g_bnstat[2*CH];
__device__ __align__(16) float g_bnscale[CH];
__device__ __align__(16) float g_bnshift[CH];
__device__ __align__(16) float g_pool[BG*CH];
__device__ __align__(16) float g_pooled[BG*CH];
__device__ int   g_cnt[BG];
__device__ __align__(16) float g_y1[BG*NHID];
__device__ __align__(16) float g_y2[BG*NHID];
__device__ int   g_bsum[128];

// ---------------- helpers ----------------
__device__ __forceinline__ float warp_sum(float v){
    #pragma unroll
    for (int o=16;o>0;o>>=1) v += __shfl_xor_sync(0xffffffffu, v, o);
    return v;
}
__device__ __forceinline__ float warp_max(float v){
    #pragma unroll
    for (int o=16;o>0;o>>=1) v = fmaxf(v, __shfl_xor_sync(0xffffffffu, v, o));
    return v;
}
__device__ __forceinline__ float4 ldh4(const __half* p){
    uint2 u = *(const uint2*)p;
    __half2 h0 = *(__half2*)&u.x;
    __half2 h1 = *(__half2*)&u.y;
    float2 f0 = __half22float2(h0);
    float2 f1 = __half22float2(h1);
    return make_float4(f0.x, f0.y, f1.x, f1.y);
}
__device__ __forceinline__ void cpa16(uint32_t s, const void* g){
    asm volatile("cp.async.ca.shared.global [%0], [%1], 16;" :: "r"(s), "l"(g));
}

// ---------------- CSR build ----------------
__global__ void k_init_deg(){
    int i = blockIdx.x*blockDim.x + threadIdx.x;
    if (i < NN) g_deg[i] = 1;   // self-loop
}
__global__ void k_count_deg(const int* __restrict__ ei){
    int e = blockIdx.x*blockDim.x + threadIdx.x;
    if (e < EE) atomicAdd(&g_deg[ei[EE + e]], 1);
}
__global__ void k_dinv(){
    int i = blockIdx.x*blockDim.x + threadIdx.x;
    if (i < NN) g_dinv[i] = rsqrtf((float)g_deg[i]);
}
__global__ void k_scan1(){
    __shared__ int sh[1024];
    int tid = threadIdx.x;
    int i = blockIdx.x*1024 + tid;
    int v = (i < NN) ? g_deg[i] : 0;
    sh[tid] = v;
    __syncthreads();
    #pragma unroll
    for (int off=1; off<1024; off<<=1){
        int t = (tid >= off) ? sh[tid-off] : 0;
        __syncthreads();
        sh[tid] += t;
        __syncthreads();
    }
    if (i < NN) g_rowptr[i] = sh[tid] - v;
    if (tid == 1023) g_bsum[blockIdx.x] = sh[1023];
}
__global__ void k_scan2(){
    if (threadIdx.x == 0){
        int acc = 0;
        for (int b=0;b<NB_SCAN;b++){ int t=g_bsum[b]; g_bsum[b]=acc; acc+=t; }
        g_rowptr[NN] = ELL;
    }
}
__global__ void k_scan3(){
    int i = blockIdx.x*blockDim.x + threadIdx.x;
    if (i < NN){
        int r = g_rowptr[i] + g_bsum[i >> 10];
        g_rowptr[i] = r;
        g_cur[i]    = r;
    }
}
__global__ void k_scatter(const int* __restrict__ ei){
    int t = blockIdx.x*blockDim.x + threadIdx.x;
    if (t < EE){
        int s = ei[t], d = ei[EE + t];
        int p = atomicAdd(&g_cur[d], 1);
        g_col[p] = s;
        g_enorm[p] = g_dinv[s] * g_dinv[d];
    } else if (t < ELL){
        int i = t - EE;
        int p = atomicAdd(&g_cur[i], 1);
        g_col[p] = i;
        float dv = g_dinv[i];
        g_enorm[p] = dv*dv;
    }
}

// ---------------- tf32 GEMM v2: cp.async double-buffered, truncated tf32 ----------------
__global__ __launch_bounds__(256) void k_gemm_tc(
    const float* __restrict__ A, const float* __restrict__ W,
    __half* __restrict__ Out, int M)
{
    __shared__ float As[2][128][20];   // K-chunk 16, stride 20 (conflict-free a-frags)
    __shared__ float Ws[2][16][136];   // stride 136 (conflict-free b-frags)
    int tid  = threadIdx.x;
    int warp = tid >> 5, lane = tid & 31;
    int g = lane >> 2, q = lane & 3;
    int wm = (warp & 3) * 32;
    int wn = (warp >> 2) * 64;
    int m0 = blockIdx.x * 128;

    float acc[2][8][4];
    #pragma unroll
    for (int mt=0;mt<2;mt++)
        #pragma unroll
        for (int nt=0;nt<8;nt++)
            #pragma unroll
            for (int i=0;i<4;i++) acc[mt][nt][i] = 0.f;

    int ar0 = tid >> 2,            as0 = tid & 3;
    int ar1 = (tid+256) >> 2,      as1 = (tid+256) & 3;
    int wr0 = tid >> 5,            ws0 = tid & 31;
    int wr1 = (tid+256) >> 5,      ws1 = (tid+256) & 31;

    #define LOAD_CHUNK(kc, buf)                                                     \
    {                                                                               \
        int ga0 = min(m0 + ar0, M-1), ga1 = min(m0 + ar1, M-1);                     \
        cpa16((uint32_t)__cvta_generic_to_shared(&As[buf][ar0][as0*4]),             \
              &A[(size_t)ga0*128 + (kc)*16 + as0*4]);                               \
        cpa16((uint32_t)__cvta_generic_to_shared(&As[buf][ar1][as1*4]),             \
              &A[(size_t)ga1*128 + (kc)*16 + as1*4]);                               \
        cpa16((uint32_t)__cvta_generic_to_shared(&Ws[buf][wr0][ws0*4]),             \
              &W[(size_t)((kc)*16 + wr0)*128 + ws0*4]);                             \
        cpa16((uint32_t)__cvta_generic_to_shared(&Ws[buf][wr1][ws1*4]),             \
              &W[(size_t)((kc)*16 + wr1)*128 + ws1*4]);                             \
        asm volatile("cp.async.commit_group;" ::: "memory");                        \
    }

    LOAD_CHUNK(0, 0);
    int buf = 0;
    for (int kc = 0; kc < 8; kc++){
        if (kc < 7){
            LOAD_CHUNK(kc+1, buf^1);
            asm volatile("cp.async.wait_group 1;" ::: "memory");
        } else {
            asm volatile("cp.async.wait_group 0;" ::: "memory");
        }
        __syncthreads();
        #pragma unroll
        for (int ks = 0; ks < 2; ks++){
            int kk = ks*8;
            uint32_t a[2][4];
            #pragma unroll
            for (int mt=0; mt<2; mt++){
                int r = wm + mt*16;
                a[mt][0] = __float_as_uint(As[buf][r+g  ][kk+q  ]);
                a[mt][1] = __float_as_uint(As[buf][r+g+8][kk+q  ]);
                a[mt][2] = __float_as_uint(As[buf][r+g  ][kk+q+4]);
                a[mt][3] = __float_as_uint(As[buf][r+g+8][kk+q+4]);
            }
            #pragma unroll
            for (int nt=0; nt<8; nt++){
                uint32_t b0 = __float_as_uint(Ws[buf][kk+q  ][wn+nt*8+g]);
                uint32_t b1 = __float_as_uint(Ws[buf][kk+q+4][wn+nt*8+g]);
                #pragma unroll
                for (int mt=0; mt<2; mt++){
                    asm volatile(
                        "mma.sync.aligned.m16n8k8.row.col.f32.tf32.tf32.f32 "
                        "{%0,%1,%2,%3}, {%4,%5,%6,%7}, {%8,%9}, {%0,%1,%2,%3};"
                        : "+f"(acc[mt][nt][0]), "+f"(acc[mt][nt][1]),
                          "+f"(acc[mt][nt][2]), "+f"(acc[mt][nt][3])
                        : "r"(a[mt][0]), "r"(a[mt][1]), "r"(a[mt][2]), "r"(a[mt][3]),
                          "r"(b0), "r"(b1));
                }
            }
        }
        __syncthreads();
        buf ^= 1;
    }
    #undef LOAD_CHUNK
    #pragma unroll
    for (int mt=0; mt<2; mt++){
        int r0 = m0 + wm + mt*16 + g;
        #pragma unroll
        for (int nt=0; nt<8; nt++){
            int c = wn + nt*8 + q*2;
            if (r0 < M)
                *(__half2*)&Out[(size_t)r0*128 + c] =
                    __floats2half2_rn(acc[mt][nt][0], acc[mt][nt][1]);
            if (r0 + 8 < M)
                *(__half2*)&Out[(size_t)(r0+8)*128 + c] =
                    __floats2half2_rn(acc[mt][nt][2], acc[mt][nt][3]);
        }
    }
}

// ---------------- fused BN+residual+GEMM v2: cp.async pipeline, dynamic smem ----------------
// smem layout (dynamic): sA[2][128][20] (raw agg -> y in place), sR[2][128][20] (res),
//                        sW[2][16][136]
#define BN_SMEM_BYTES ((2*128*20 + 2*128*20 + 2*16*136) * 4)
__global__ __launch_bounds__(256) void k_gemm_tc_bn(
    const float* __restrict__ agg, const float* __restrict__ res,
    float* __restrict__ xout,
    const float* __restrict__ W, __half* __restrict__ Out, int M)
{
    extern __shared__ float dsm[];
    float (*sA)[128][20] = (float(*)[128][20])dsm;
    float (*sR)[128][20] = (float(*)[128][20])(dsm + 2*128*20);
    float (*sW)[16][136] = (float(*)[16][136])(dsm + 4*128*20);

    int tid  = threadIdx.x;
    int warp = tid >> 5, lane = tid & 31;
    int g = lane >> 2, q = lane & 3;
    int wm = (warp & 3) * 32;
    int wn = (warp >> 2) * 64;
    int m0 = blockIdx.x * 128;

    float acc[2][8][4];
    #pragma unroll
    for (int mt=0;mt<2;mt++)
        #pragma unroll
        for (int nt=0;nt<8;nt++)
            #pragma unroll
            for (int i=0;i<4;i++) acc[mt][nt][i] = 0.f;

    int ar0 = tid >> 2,            as0 = tid & 3;
    int ar1 = (tid+256) >> 2,      as1 = (tid+256) & 3;
    int wr0 = tid >> 5,            ws0 = tid & 31;
    int wr1 = (tid+256) >> 5,      ws1 = (tid+256) & 31;
    // transform assignment: column-major (bank-conflict-free): row 0..127, col offset 0/8
    int tr = tid & 127;
    int tc = (tid >> 7) * 8;
    int grow = m0 + tr;

    #define LOAD_CHUNK_BN(kc, b)                                                    \
    {                                                                               \
        int ga0 = min(m0 + ar0, M-1), ga1 = min(m0 + ar1, M-1);                     \
        cpa16((uint32_t)__cvta_generic_to_shared(&sA[b][ar0][as0*4]),               \
              &agg[(size_t)ga0*128 + (kc)*16 + as0*4]);                             \
        cpa16((uint32_t)__cvta_generic_to_shared(&sA[b][ar1][as1*4]),               \
              &agg[(size_t)ga1*128 + (kc)*16 + as1*4]);                             \
        cpa16((uint32_t)__cvta_generic_to_shared(&sR[b][ar0][as0*4]),               \
              &res[(size_t)ga0*128 + (kc)*16 + as0*4]);                             \
        cpa16((uint32_t)__cvta_generic_to_shared(&sR[b][ar1][as1*4]),               \
              &res[(size_t)ga1*128 + (kc)*16 + as1*4]);                             \
        cpa16((uint32_t)__cvta_generic_to_shared(&sW[b][wr0][ws0*4]),               \
              &W[(size_t)((kc)*16 + wr0)*128 + ws0*4]);                             \
        cpa16((uint32_t)__cvta_generic_to_shared(&sW[b][wr1][ws1*4]),               \
              &W[(size_t)((kc)*16 + wr1)*128 + ws1*4]);                             \
        asm volatile("cp.async.commit_group;" ::: "memory");                        \
    }

    LOAD_CHUNK_BN(0, 0);
    int buf = 0;
    for (int kc = 0; kc < 8; kc++){
        if (kc < 7){
            LOAD_CHUNK_BN(kc+1, buf^1);
            asm volatile("cp.async.wait_group 1;" ::: "memory");
        } else {
            asm volatile("cp.async.wait_group 0;" ::: "memory");
        }
        __syncthreads();
        // transform: y = relu(agg*sc+sh) + res; write xout + back into sA (in place)
        {
            int cbase = kc*16 + tc;
            float4 sc0 = *(const float4*)&g_bnscale[cbase];
            float4 sc1 = *(const float4*)&g_bnscale[cbase+4];
            float4 sh0 = *(const float4*)&g_bnshift[cbase];
            float4 sh1 = *(const float4*)&g_bnshift[cbase+4];
            float4 a0 = *(float4*)&sA[buf][tr][tc];
            float4 a1 = *(float4*)&sA[buf][tr][tc+4];
            float4 r0 = *(float4*)&sR[buf][tr][tc];
            float4 r1 = *(float4*)&sR[buf][tr][tc+4];
            float4 y0, y1;
            y0.x = fmaxf(fmaf(a0.x, sc0.x, sh0.x), 0.f) + r0.x;
            y0.y = fmaxf(fmaf(a0.y, sc0.y, sh0.y), 0.f) + r0.y;
            y0.z = fmaxf(fmaf(a0.z, sc0.z, sh0.z), 0.f) + r0.z;
            y0.w = fmaxf(fmaf(a0.w, sc0.w, sh0.w), 0.f) + r0.w;
            y1.x = fmaxf(fmaf(a1.x, sc1.x, sh1.x), 0.f) + r1.x;
            y1.y = fmaxf(fmaf(a1.y, sc1.y, sh1.y), 0.f) + r1.y;
            y1.z = fmaxf(fmaf(a1.z, sc1.z, sh1.z), 0.f) + r1.z;
            y1.w = fmaxf(fmaf(a1.w, sc1.w, sh1.w), 0.f) + r1.w;
            *(float4*)&sA[buf][tr][tc]   = y0;
            *(float4*)&sA[buf][tr][tc+4] = y1;
            if (grow < M){
                size_t off = (size_t)grow*128 + cbase;
                *(float4*)&xout[off]   = y0;
                *(float4*)&xout[off+4] = y1;
            }
        }
        __syncthreads();
        #pragma unroll
        for (int ks = 0; ks < 2; ks++){
            int kk = ks*8;
            uint32_t a[2][4];
            #pragma unroll
            for (int mt=0; mt<2; mt++){
                int r = wm + mt*16;
                a[mt][0] = __float_as_uint(sA[buf][r+g  ][kk+q  ]);
                a[mt][1] = __float_as_uint(sA[buf][r+g+8][kk+q  ]);
                a[mt][2] = __float_as_uint(sA[buf][r+g  ][kk+q+4]);
                a[mt][3] = __float_as_uint(sA[buf][r+g+8][kk+q+4]);
            }
            #pragma unroll
            for (int nt=0; nt<8; nt++){
                uint32_t b0 = __float_as_uint(sW[buf][kk+q  ][wn+nt*8+g]);
                uint32_t b1 = __float_as_uint(sW[buf][kk+q+4][wn+nt*8+g]);
                #pragma unroll
                for (int mt=0; mt<2; mt++){
                    asm volatile(
                        "mma.sync.aligned.m16n8k8.row.col.f32.tf32.tf32.f32 "
                        "{%0,%1,%2,%3}, {%4,%5,%6,%7}, {%8,%9}, {%0,%1,%2,%3};"
                        : "+f"(acc[mt][nt][0]), "+f"(acc[mt][nt][1]),
                          "+f"(acc[mt][nt][2]), "+f"(acc[mt][nt][3])
                        : "r"(a[mt][0]), "r"(a[mt][1]), "r"(a[mt][2]), "r"(a[mt][3]),
                          "r"(b0), "r"(b1));
                }
            }
        }
        __syncthreads();
        buf ^= 1;
    }
    #undef LOAD_CHUNK_BN
    #pragma unroll
    for (int mt=0; mt<2; mt++){
        int r0 = m0 + wm + mt*16 + g;
        #pragma unroll
        for (int nt=0; nt<8; nt++){
            int c = wn + nt*8 + q*2;
            if (r0 < M)
                *(__half2*)&Out[(size_t)r0*128 + c] =
                    __floats2half2_rn(acc[mt][nt][0], acc[mt][nt][1]);
            if (r0 + 8 < M)
                *(__half2*)&Out[(size_t)(r0+8)*128 + c] =
                    __floats2half2_rn(acc[mt][nt][2], acc[mt][nt][3]);
        }
    }
}

// ---------------- small-tile fp32 GEMM (MLP head) ----------------
__global__ __launch_bounds__(256) void k_gemm_s(
    const float* __restrict__ A, const float* __restrict__ Bw,
    const float* __restrict__ bias, float* __restrict__ Out,
    int M, int Nn, int K, int relu)
{
    __shared__ float As[16][33];
    __shared__ float Bs[16][68];
    int tid = threadIdx.x;
    int m0 = blockIdx.x*32, n0 = blockIdx.y*64;
    int ty = tid >> 4;
    int tx = tid & 15;
    float acc[2][4];
    #pragma unroll
    for (int r=0;r<2;r++)
        #pragma unroll
        for (int c=0;c<4;c++) acc[r][c] = 0.f;

    for (int k0=0; k0<K; k0+=16){
        {
            int idx = tid * 2;
            int row = idx >> 4;
            int kk  = idx & 15;
            float2 v = *(const float2*)&A[(size_t)(m0+row)*K + k0 + kk];
            As[kk  ][row] = v.x;
            As[kk+1][row] = v.y;
        }
        {
            int kk = tid >> 4;
            int c  = (tid & 15) * 4;
            float4 v = *(const float4*)&Bw[(size_t)(k0+kk)*Nn + n0 + c];
            *(float4*)&Bs[kk][c] = v;
        }
        __syncthreads();
        #pragma unroll
        for (int kk=0; kk<16; kk++){
            float a0 = As[kk][ty];
            float a1 = As[kk][ty+16];
            float4 bv = *(float4*)&Bs[kk][tx*4];
            acc[0][0] = fmaf(a0, bv.x, acc[0][0]);
            acc[0][1] = fmaf(a0, bv.y, acc[0][1]);
            acc[0][2] = fmaf(a0, bv.z, acc[0][2]);
            acc[0][3] = fmaf(a0, bv.w, acc[0][3]);
            acc[1][0] = fmaf(a1, bv.x, acc[1][0]);
            acc[1][1] = fmaf(a1, bv.y, acc[1][1]);
            acc[1][2] = fmaf(a1, bv.z, acc[1][2]);
            acc[1][3] = fmaf(a1, bv.w, acc[1][3]);
        }
        __syncthreads();
    }
    #pragma unroll
    for (int r=0;r<2;r++){
        int row = m0 + ty + r*16;
        int cc  = n0 + tx*4;
        float4 o = make_float4(acc[r][0], acc[r][1], acc[r][2], acc[r][3]);
        o.x += bias[cc]; o.y += bias[cc+1]; o.z += bias[cc+2]; o.w += bias[cc+3];
        if (relu){ o.x=fmaxf(o.x,0.f); o.y=fmaxf(o.y,0.f); o.z=fmaxf(o.z,0.f); o.w=fmaxf(o.w,0.f); }
        *(float4*)&Out[(size_t)row*Nn + cc] = o;
    }
}

// ---------------- GCN aggregation (at machine gather limit) ----------------
__global__ __launch_bounds__(256, 4) void k_gcn_agg(
    const __half* __restrict__ h, const float* __restrict__ bias, int nmax)
{
    __shared__ float4 rsum[8][32];
    __shared__ float4 rsq [8][32];
    int tid  = threadIdx.x;
    int warp = tid >> 5, lane = tid & 31;
    int node = blockIdx.x*8 + warp;
    float4 acc = make_float4(0.f,0.f,0.f,0.f);
    if (node < nmax){
        int p0 = g_rowptr[node], p1 = g_rowptr[node+1];
        const __half* hb = h + lane*4;
        int p = p0;
        for (; p + 8 <= p1; p += 8){
            int ss[8]; float ww[8];
            #pragma unroll
            for (int j=0;j<8;j++){ ss[j] = g_col[p+j]; ww[j] = g_enorm[p+j]; }
            float4 vv[8];
            #pragma unroll
            for (int j=0;j<8;j++) vv[j] = ldh4(hb + (size_t)ss[j]*CH);
            #pragma unroll
            for (int j=0;j<8;j++){
                acc.x = fmaf(ww[j], vv[j].x, acc.x);
                acc.y = fmaf(ww[j], vv[j].y, acc.y);
                acc.z = fmaf(ww[j], vv[j].z, acc.z);
                acc.w = fmaf(ww[j], vv[j].w, acc.w);
            }
        }
        for (; p < p1; p++){
            int s = g_col[p];
            float w = g_enorm[p];
            float4 v = ldh4(hb + (size_t)s*CH);
            acc.x = fmaf(w, v.x, acc.x);
            acc.y = fmaf(w, v.y, acc.y);
            acc.z = fmaf(w, v.z, acc.z);
            acc.w = fmaf(w, v.w, acc.w);
        }
        float4 bb = ((const float4*)bias)[lane];
        acc.x += bb.x; acc.y += bb.y; acc.z += bb.z; acc.w += bb.w;
        *((float4*)g_agg + (size_t)node*32 + lane) = acc;
        rsum[warp][lane] = acc;
        rsq [warp][lane] = make_float4(acc.x*acc.x, acc.y*acc.y, acc.z*acc.z, acc.w*acc.w);
    } else {
        rsum[warp][lane] = make_float4(0.f,0.f,0.f,0.f);
        rsq [warp][lane] = make_float4(0.f,0.f,0.f,0.f);
    }
    __syncthreads();
    if (tid < CH){
        const float* ps = (const float*)rsum;
        const float* pq = (const float*)rsq;
        float s = 0.f, q = 0.f;
        #pragma unroll
        for (int w=0; w<8; w++){ s += ps[w*128 + tid]; q += pq[w*128 + tid]; }
        atomicAdd(&g_bnstat[tid],      s);
        atomicAdd(&g_bnstat[CH + tid], q);
    }
}

// ---------------- BN finalize (self-zeroing) ----------------
__global__ void k_bnfin(const float* __restrict__ g, const float* __restrict__ be){
    int c = threadIdx.x;
    float mean = g_bnstat[c] * (1.f/NN);
    float var  = g_bnstat[CH+c] * (1.f/NN) - mean*mean;
    float sc   = g[c] * rsqrtf(var + 1e-5f);
    g_bnscale[c] = sc;
    g_bnshift[c] = be[c] - mean*sc;
    g_bnstat[c] = 0.f;
    g_bnstat[CH + c] = 0.f;
}

// ---------------- GAT: per-node attention scalars (fp16 h) ----------------
__global__ void k_esed(const __half* __restrict__ h, const float* __restrict__ as,
                       const float* __restrict__ ad)
{
    int gt = blockIdx.x*blockDim.x + threadIdx.x;
    int node = gt >> 5, lane = gt & 31;
    if (node >= NN) return;
    float4 v = ldh4(h + (size_t)node*CH + lane*4);
    float4 a = ((const float4*)as)[lane];
    float4 d = ((const float4*)ad)[lane];
    float es = v.x*a.x + v.y*a.y + v.z*a.z + v.w*a.w;
    float ed = v.x*d.x + v.y*d.y + v.z*d.z + v.w*d.w;
    es = warp_sum(es); ed = warp_sum(ed);
    if (lane == 0){ g_es[node] = es; g_ed[node] = ed; }
}

// ---------------- GAT aggregation ----------------
__global__ __launch_bounds__(256, 4) void k_gat_agg(
    const __half* __restrict__ h, const float* __restrict__ bias)
{
    __shared__ float4 rsum[8][32];
    __shared__ float4 rsq [8][32];
    int tid = threadIdx.x;
    int warp = tid >> 5, lane = tid & 31;
    int node = blockIdx.x*8 + warp;
    float4 acc = make_float4(0.f,0.f,0.f,0.f);
    if (node < NN){
        int p0 = g_rowptr[node], p1 = g_rowptr[node+1];
        float edi = g_ed[node];
        float m = -1e30f;
        for (int p = p0 + lane; p < p1; p += 32){
            float e = g_es[g_col[p]] + edi;
            e = (e > 0.f) ? e : 0.2f*e;
            m = fmaxf(m, e);
        }
        m = warp_max(m);
        float s = 0.f;
        int p = p0;
        for (; p + 4 <= p1; p += 4){
            int ss[4];
            #pragma unroll
            for (int j=0;j<4;j++) ss[j] = g_col[p+j];
            float ex[4];
            #pragma unroll
            for (int j=0;j<4;j++){
                float e = g_es[ss[j]] + edi;
                e = (e > 0.f) ? e : 0.2f*e;
                ex[j] = expf(e - m);
            }
            float4 vv[4];
            #pragma unroll
            for (int j=0;j<4;j++) vv[j] = ldh4(h + (size_t)ss[j]*CH + lane*4);
            #pragma unroll
            for (int j=0;j<4;j++){
                s += ex[j];
                acc.x = fmaf(ex[j], vv[j].x, acc.x);
                acc.y = fmaf(ex[j], vv[j].y, acc.y);
                acc.z = fmaf(ex[j], vv[j].z, acc.z);
                acc.w = fmaf(ex[j], vv[j].w, acc.w);
            }
        }
        for (; p < p1; p++){
            int sc = g_col[p];
            float e = g_es[sc] + edi;
            e = (e > 0.f) ? e : 0.2f*e;
            float exv = expf(e - m);
            s += exv;
            float4 v = ldh4(h + (size_t)sc*CH + lane*4);
            acc.x = fmaf(exv, v.x, acc.x);
            acc.y = fmaf(exv, v.y, acc.y);
            acc.z = fmaf(exv, v.z, acc.z);
            acc.w = fmaf(exv, v.w, acc.w);
        }
        float inv = 1.f / (s + 1e-16f);
        float4 bb = ((const float4*)bias)[lane];
        acc.x = acc.x*inv + bb.x;
        acc.y = acc.y*inv + bb.y;
        acc.z = acc.z*inv + bb.z;
        acc.w = acc.w*inv + bb.w;
        *((float4*)g_agg + (size_t)node*32 + lane) = acc;
        rsum[warp][lane] = acc;
        rsq [warp][lane] = make_float4(acc.x*acc.x, acc.y*acc.y, acc.z*acc.z, acc.w*acc.w);
    } else {
        rsum[warp][lane] = make_float4(0.f,0.f,0.f,0.f);
        rsq [warp][lane] = make_float4(0.f,0.f,0.f,0.f);
    }
    __syncthreads();
    if (tid < CH){
        const float* ps = (const float*)rsum;
        const float* pq = (const float*)rsq;
        float s = 0.f, q = 0.f;
        #pragma unroll
        for (int w=0; w<8; w++){ s += ps[w*128 + tid]; q += pq[w*128 + tid]; }
        atomicAdd(&g_bnstat[tid],      s);
        atomicAdd(&g_bnstat[CH + tid], q);
    }
}

// ---------------- pooling ----------------
__global__ void k_cnt(const int* __restrict__ batch){
    int i = blockIdx.x*blockDim.x + threadIdx.x;
    if (i < NN) atomicAdd(&g_cnt[batch[i]], 1);
}
__global__ void k_pool_bn(const int* __restrict__ batch,
                          const float* __restrict__ agg, const float* __restrict__ res)
{
    int gw   = (blockIdx.x*blockDim.x + threadIdx.x) >> 5;
    int lane = threadIdx.x & 31;
    int n0 = gw * 16;
    if (n0 >= NN) return;
    int nend = min(n0 + 16, NN);
    float4 sc = ((const float4*)g_bnscale)[lane];
    float4 sh = ((const float4*)g_bnshift)[lane];
    int curb = batch[n0];
    float4 acc = make_float4(0.f,0.f,0.f,0.f);
    for (int n=n0; n<nend; n++){
        int b = batch[n];
        if (b != curb){
            int base = curb*CH + lane*4;
            atomicAdd(&g_pool[base+0], acc.x);
            atomicAdd(&g_pool[base+1], acc.y);
            atomicAdd(&g_pool[base+2], acc.z);
            atomicAdd(&g_pool[base+3], acc.w);
            acc = make_float4(0.f,0.f,0.f,0.f);
            curb = b;
        }
        size_t off = (size_t)n*32 + lane;
        float4 a = ((const float4*)agg)[off];
        float4 r = ((const float4*)res)[off];
        acc.x += fmaxf(fmaf(a.x, sc.x, sh.x), 0.f) + r.x;
        acc.y += fmaxf(fmaf(a.y, sc.y, sh.y), 0.f) + r.y;
        acc.z += fmaxf(fmaf(a.z, sc.z, sh.z), 0.f) + r.z;
        acc.w += fmaxf(fmaf(a.w, sc.w, sh.w), 0.f) + r.w;
    }
    int base = curb*CH + lane*4;
    atomicAdd(&g_pool[base+0], acc.x);
    atomicAdd(&g_pool[base+1], acc.y);
    atomicAdd(&g_pool[base+2], acc.z);
    atomicAdd(&g_pool[base+3], acc.w);
}
__global__ void k_pooldiv(){
    int b = blockIdx.x, c = threadIdx.x;
    float inv = 1.f / fmaxf((float)g_cnt[b], 1.f);
    g_pooled[b*CH + c] = g_pool[b*CH + c] * inv;
    g_pool[b*CH + c] = 0.f;
    if (c == 0) g_cnt[b] = 0;
}

// ---------------- launch ----------------
extern "C" void kernel_launch(void* const* d_in, const int* in_sizes, int n_in,
                              void* d_out, int out_size)
{
    const float* x     = (const float*)d_in[0];
    const int*   ei    = (const int*)  d_in[1];
    const int*   batch = (const int*)  d_in[2];
    const float* W1  = (const float*)d_in[3];
    const float* b1  = (const float*)d_in[4];
    const float* gm1 = (const float*)d_in[5];
    const float* be1 = (const float*)d_in[6];
    const float* W2  = (const float*)d_in[7];
    const float* b2  = (const float*)d_in[8];
    const float* gm2 = (const float*)d_in[9];
    const float* be2 = (const float*)d_in[10];
    const float* W3  = (const float*)d_in[11];
    const float* b3  = (const float*)d_in[12];
    const float* gm3 = (const float*)d_in[13];
    const float* be3 = (const float*)d_in[14];
    const float* Wa   = (const float*)d_in[15];
    const float* asrc = (const float*)d_in[16];
    const float* adst = (const float*)d_in[17];
    const float* ba   = (const float*)d_in[18];
    const float* ga   = (const float*)d_in[19];
    const float* bea  = (const float*)d_in[20];
    const float* Wh1 = (const float*)d_in[21];
    const float* bh1 = (const float*)d_in[22];
    const float* Wm0 = (const float*)d_in[23];
    const float* bm0 = (const float*)d_in[24];
    const float* Wm1 = (const float*)d_in[25];
    const float* bm1 = (const float*)d_in[26];
    const float* Wo  = (const float*)d_in[27];
    const float* bo  = (const float*)d_in[28];

    __half *ph;
    float *px, *pagg, *ppooled, *py1, *py2;
    cudaGetSymbolAddress((void**)&ph,      g_h16);
    cudaGetSymbolAddress((void**)&px,      g_x);
    cudaGetSymbolAddress((void**)&pagg,    g_agg);
    cudaGetSymbolAddress((void**)&ppooled, g_pooled);
    cudaGetSymbolAddress((void**)&py1,     g_y1);
    cudaGetSymbolAddress((void**)&py2,     g_y2);

    cudaFuncSetAttribute(k_gemm_tc_bn,
                         cudaFuncAttributeMaxDynamicSharedMemorySize, BN_SMEM_BYTES);

    const int T = 256;
    const int TC_GX  = (NN + 127) / 128;
    const int AGG_B  = (NN + 7) / 8;

    // ---- CSR build ----
    k_init_deg <<<(NN+T-1)/T, T>>>();
    k_count_deg<<<(EE+T-1)/T, T>>>(ei);
    k_dinv     <<<(NN+T-1)/T, T>>>();
    k_scan1    <<<NB_SCAN, 1024>>>();
    k_scan2    <<<1, 32>>>();
    k_scan3    <<<(NN+T-1)/T, T>>>();
    k_scatter  <<<(ELL+T-1)/T, T>>>(ei);

    // ---- GCN layer 1 ----
    k_gemm_tc<<<TC_GX, 256>>>(x, W1, ph, NN);
    k_gcn_agg<<<AGG_B, 256>>>(ph, b1, NN);
    k_bnfin<<<1, CH>>>(gm1, be1);

    // ---- layer 2: fused apply(layer1) + GEMM ----
    k_gemm_tc_bn<<<TC_GX, 256, BN_SMEM_BYTES>>>(pagg, x, px, W2, ph, NN);
    k_gcn_agg<<<AGG_B, 256>>>(ph, b2, NN);
    k_bnfin<<<1, CH>>>(gm2, be2);

    // ---- layer 3: fused apply(layer2) + GEMM ----
    k_gemm_tc_bn<<<TC_GX, 256, BN_SMEM_BYTES>>>(pagg, px, px, W3, ph, NN);
    k_gcn_agg<<<AGG_B, 256>>>(ph, b3, NN);
    k_bnfin<<<1, CH>>>(gm3, be3);

    // ---- GAT layer: fused apply(layer3) + GEMM ----
    k_gemm_tc_bn<<<TC_GX, 256, BN_SMEM_BYTES>>>(pagg, px, px, Wa, ph, NN);
    k_esed<<<(NN*32+T-1)/T, T>>>(ph, asrc, adst);
    k_gat_agg<<<AGG_B, 256>>>(ph, ba);
    k_bnfin<<<1, CH>>>(ga, bea);

    // ---- global mean pool (fused with final BN apply) ----
    k_cnt<<<(NN+T-1)/T, T>>>(batch);
    {
        int warps = (NN + 15) / 16;
        int blocks = (warps*32 + T - 1) / T;
        k_pool_bn<<<blocks, T>>>(batch, pagg, px);
    }
    k_pooldiv<<<BG, CH>>>();

    // ---- MLP head ----
    k_gemm_s<<<dim3(BG/32, NHID/64), 256>>>(ppooled, Wh1, bh1, py1, BG, NHID, CH,   1);
    k_gemm_s<<<dim3(BG/32, NHID/64), 256>>>(py1,     Wm0, bm0, py2, BG, NHID, NHID, 1);
    k_gemm_s<<<dim3(BG/32, NHID/64), 256>>>(py2,     Wm1, bm1, py1, BG, NHID, NHID, 1);
    k_gemm_s<<<dim3(BG/32, NOUT/64), 256>>>(py1,     Wo,  bo,  (float*)d_out, BG, NOUT, NHID, 0);
}

// round 17
// speedup vs baseline: 1.0294x; 1.0294x over previous
#include <cuda_runtime.h>
#include <cuda_fp16.h>
#include <cstdint>
#include <cstddef>

// ---------------- problem constants ----------------
#define NN   100000
#define EE   1600000
#define ELL  (EE+NN)
#define CH   128
#define BG   512
#define NHID 512
#define NOUT 256
#define NB_SCAN 98   // ceil(NN/1024)

// ---------------- scratch (__device__ globals; no allocs allowed) ----------------
__device__ __align__(16) __half g_h16[(size_t)NN*CH];
__device__ __align__(16) float g_agg[(size_t)NN*CH];
__device__ __align__(16) float g_x  [(size_t)NN*CH];
__device__ int   g_deg[NN];
__device__ float g_dinv[NN];
__device__ int   g_rowptr[NN+1];
__device__ int   g_cur[NN];
__device__ int   g_col[ELL];
__device__ float g_enorm[ELL];
__device__ float g_es[NN];
__device__ float g_ed[NN];
__device__ __align__(16) float g_bnstat[2*CH];
__device__ __align__(16) float g_bnscale[CH];
__device__ __align__(16) float g_bnshift[CH];
__device__ __align__(16) float g_pool[BG*CH];
__device__ __align__(16) float g_pooled[BG*CH];
__device__ int   g_cnt[BG];
__device__ __align__(16) float g_y1[BG*NHID];
__device__ __align__(16) float g_y2[BG*NHID];
__device__ int   g_bsum[128];

// ---------------- helpers ----------------
__device__ __forceinline__ float warp_sum(float v){
    #pragma unroll
    for (int o=16;o>0;o>>=1) v += __shfl_xor_sync(0xffffffffu, v, o);
    return v;
}
__device__ __forceinline__ float warp_max(float v){
    #pragma unroll
    for (int o=16;o>0;o>>=1) v = fmaxf(v, __shfl_xor_sync(0xffffffffu, v, o));
    return v;
}
__device__ __forceinline__ float4 ldh4(const __half* p){
    uint2 u = *(const uint2*)p;
    __half2 h0 = *(__half2*)&u.x;
    __half2 h1 = *(__half2*)&u.y;
    float2 f0 = __half22float2(h0);
    float2 f1 = __half22float2(h1);
    return make_float4(f0.x, f0.y, f1.x, f1.y);
}
__device__ __forceinline__ void cpa16(uint32_t s, const void* g){
    asm volatile("cp.async.ca.shared.global [%0], [%1], 16;" :: "r"(s), "l"(g));
}

// ---------------- CSR build ----------------
__global__ void k_init_deg(){
    int i = blockIdx.x*blockDim.x + threadIdx.x;
    if (i < NN) g_deg[i] = 1;   // self-loop
}
__global__ void k_count_deg(const int* __restrict__ ei){
    int e = blockIdx.x*blockDim.x + threadIdx.x;
    if (e < EE) atomicAdd(&g_deg[ei[EE + e]], 1);
}
__global__ void k_dinv(){
    int i = blockIdx.x*blockDim.x + threadIdx.x;
    if (i < NN) g_dinv[i] = rsqrtf((float)g_deg[i]);
}
__global__ void k_scan1(){
    __shared__ int sh[1024];
    int tid = threadIdx.x;
    int i = blockIdx.x*1024 + tid;
    int v = (i < NN) ? g_deg[i] : 0;
    sh[tid] = v;
    __syncthreads();
    #pragma unroll
    for (int off=1; off<1024; off<<=1){
        int t = (tid >= off) ? sh[tid-off] : 0;
        __syncthreads();
        sh[tid] += t;
        __syncthreads();
    }
    if (i < NN) g_rowptr[i] = sh[tid] - v;
    if (tid == 1023) g_bsum[blockIdx.x] = sh[1023];
}
__global__ void k_scan2(){
    if (threadIdx.x == 0){
        int acc = 0;
        for (int b=0;b<NB_SCAN;b++){ int t=g_bsum[b]; g_bsum[b]=acc; acc+=t; }
        g_rowptr[NN] = ELL;
    }
}
__global__ void k_scan3(){
    int i = blockIdx.x*blockDim.x + threadIdx.x;
    if (i < NN){
        int r = g_rowptr[i] + g_bsum[i >> 10];
        g_rowptr[i] = r;
        g_cur[i]    = r;
    }
}
__global__ void k_scatter(const int* __restrict__ ei){
    int t = blockIdx.x*blockDim.x + threadIdx.x;
    if (t < EE){
        int s = ei[t], d = ei[EE + t];
        int p = atomicAdd(&g_cur[d], 1);
        g_col[p] = s;
        g_enorm[p] = g_dinv[s] * g_dinv[d];
    } else if (t < ELL){
        int i = t - EE;
        int p = atomicAdd(&g_cur[i], 1);
        g_col[p] = i;
        float dv = g_dinv[i];
        g_enorm[p] = dv*dv;
    }
}

// ---------------- tf32 GEMM v2: cp.async double-buffered, truncated tf32 ----------------
__global__ __launch_bounds__(256) void k_gemm_tc(
    const float* __restrict__ A, const float* __restrict__ W,
    __half* __restrict__ Out, int M)
{
    __shared__ float As[2][128][20];
    __shared__ float Ws[2][16][136];
    int tid  = threadIdx.x;
    int warp = tid >> 5, lane = tid & 31;
    int g = lane >> 2, q = lane & 3;
    int wm = (warp & 3) * 32;
    int wn = (warp >> 2) * 64;
    int m0 = blockIdx.x * 128;

    float acc[2][8][4];
    #pragma unroll
    for (int mt=0;mt<2;mt++)
        #pragma unroll
        for (int nt=0;nt<8;nt++)
            #pragma unroll
            for (int i=0;i<4;i++) acc[mt][nt][i] = 0.f;

    int ar0 = tid >> 2,            as0 = tid & 3;
    int ar1 = (tid+256) >> 2,      as1 = (tid+256) & 3;
    int wr0 = tid >> 5,            ws0 = tid & 31;
    int wr1 = (tid+256) >> 5,      ws1 = (tid+256) & 31;

    #define LOAD_CHUNK(kc, buf)                                                     \
    {                                                                               \
        int ga0 = min(m0 + ar0, M-1), ga1 = min(m0 + ar1, M-1);                     \
        cpa16((uint32_t)__cvta_generic_to_shared(&As[buf][ar0][as0*4]),             \
              &A[(size_t)ga0*128 + (kc)*16 + as0*4]);                               \
        cpa16((uint32_t)__cvta_generic_to_shared(&As[buf][ar1][as1*4]),             \
              &A[(size_t)ga1*128 + (kc)*16 + as1*4]);                               \
        cpa16((uint32_t)__cvta_generic_to_shared(&Ws[buf][wr0][ws0*4]),             \
              &W[(size_t)((kc)*16 + wr0)*128 + ws0*4]);                             \
        cpa16((uint32_t)__cvta_generic_to_shared(&Ws[buf][wr1][ws1*4]),             \
              &W[(size_t)((kc)*16 + wr1)*128 + ws1*4]);                             \
        asm volatile("cp.async.commit_group;" ::: "memory");                        \
    }

    LOAD_CHUNK(0, 0);
    int buf = 0;
    for (int kc = 0; kc < 8; kc++){
        if (kc < 7){
            LOAD_CHUNK(kc+1, buf^1);
            asm volatile("cp.async.wait_group 1;" ::: "memory");
        } else {
            asm volatile("cp.async.wait_group 0;" ::: "memory");
        }
        __syncthreads();
        #pragma unroll
        for (int ks = 0; ks < 2; ks++){
            int kk = ks*8;
            uint32_t a[2][4];
            #pragma unroll
            for (int mt=0; mt<2; mt++){
                int r = wm + mt*16;
                a[mt][0] = __float_as_uint(As[buf][r+g  ][kk+q  ]);
                a[mt][1] = __float_as_uint(As[buf][r+g+8][kk+q  ]);
                a[mt][2] = __float_as_uint(As[buf][r+g  ][kk+q+4]);
                a[mt][3] = __float_as_uint(As[buf][r+g+8][kk+q+4]);
            }
            #pragma unroll
            for (int nt=0; nt<8; nt++){
                uint32_t b0 = __float_as_uint(Ws[buf][kk+q  ][wn+nt*8+g]);
                uint32_t b1 = __float_as_uint(Ws[buf][kk+q+4][wn+nt*8+g]);
                #pragma unroll
                for (int mt=0; mt<2; mt++){
                    asm volatile(
                        "mma.sync.aligned.m16n8k8.row.col.f32.tf32.tf32.f32 "
                        "{%0,%1,%2,%3}, {%4,%5,%6,%7}, {%8,%9}, {%0,%1,%2,%3};"
                        : "+f"(acc[mt][nt][0]), "+f"(acc[mt][nt][1]),
                          "+f"(acc[mt][nt][2]), "+f"(acc[mt][nt][3])
                        : "r"(a[mt][0]), "r"(a[mt][1]), "r"(a[mt][2]), "r"(a[mt][3]),
                          "r"(b0), "r"(b1));
                }
            }
        }
        __syncthreads();
        buf ^= 1;
    }
    #undef LOAD_CHUNK
    #pragma unroll
    for (int mt=0; mt<2; mt++){
        int r0 = m0 + wm + mt*16 + g;
        #pragma unroll
        for (int nt=0; nt<8; nt++){
            int c = wn + nt*8 + q*2;
            if (r0 < M)
                *(__half2*)&Out[(size_t)r0*128 + c] =
                    __floats2half2_rn(acc[mt][nt][0], acc[mt][nt][1]);
            if (r0 + 8 < M)
                *(__half2*)&Out[(size_t)(r0+8)*128 + c] =
                    __floats2half2_rn(acc[mt][nt][2], acc[mt][nt][3]);
        }
    }
}

// ---------------- fused BN-apply + residual + tf32 GEMM (R14 form, raw tf32) ----------------
__global__ __launch_bounds__(256) void k_gemm_tc_bn(
    const float* __restrict__ agg, const float* __restrict__ res,
    float* __restrict__ xout,
    const float* __restrict__ W, __half* __restrict__ Out, int M)
{
    __shared__ float As[128][36];
    __shared__ float Ws[32][136];
    int tid  = threadIdx.x;
    int warp = tid >> 5, lane = tid & 31;
    int g = lane >> 2, q = lane & 3;
    int wm = (warp & 3) * 32;
    int wn = (warp >> 2) * 64;
    int m0 = blockIdx.x * 128;

    float acc[2][8][4];
    #pragma unroll
    for (int mt=0;mt<2;mt++)
        #pragma unroll
        for (int nt=0;nt<8;nt++)
            #pragma unroll
            for (int i=0;i<4;i++) acc[mt][nt][i] = 0.f;

    for (int k0 = 0; k0 < 128; k0 += 32){
        {
            int r = tid >> 3;
            int c = (tid & 7) * 4;
            float4 sc = *(const float4*)&g_bnscale[k0 + c];
            float4 sh = *(const float4*)&g_bnshift[k0 + c];
            #pragma unroll
            for (int rr = 0; rr < 128; rr += 32){
                int row = m0 + r + rr;
                float4 y = make_float4(0.f,0.f,0.f,0.f);
                if (row < M){
                    size_t off = (size_t)row*128 + k0 + c;
                    float4 a = *(const float4*)&agg[off];
                    float4 rv = *(const float4*)&res[off];
                    y.x = fmaxf(fmaf(a.x, sc.x, sh.x), 0.f) + rv.x;
                    y.y = fmaxf(fmaf(a.y, sc.y, sh.y), 0.f) + rv.y;
                    y.z = fmaxf(fmaf(a.z, sc.z, sh.z), 0.f) + rv.z;
                    y.w = fmaxf(fmaf(a.w, sc.w, sh.w), 0.f) + rv.w;
                    *(float4*)&xout[off] = y;
                }
                As[r+rr][c+0] = y.x;
                As[r+rr][c+1] = y.y;
                As[r+rr][c+2] = y.z;
                As[r+rr][c+3] = y.w;
            }
        }
        {
            #pragma unroll
            for (int i = 0; i < 4; i++){
                int idx = tid + i*256;
                int row = idx >> 5;
                int c   = (idx & 31) * 4;
                float4 v = *(const float4*)&W[(size_t)(k0+row)*128 + c];
                *(float4*)&Ws[row][c] = v;
            }
        }
        __syncthreads();
        #pragma unroll
        for (int ks = 0; ks < 4; ks++){
            int kk = ks*8;
            uint32_t a[2][4];
            #pragma unroll
            for (int mt=0; mt<2; mt++){
                int r = wm + mt*16;
                a[mt][0] = __float_as_uint(As[r+g  ][kk+q  ]);
                a[mt][1] = __float_as_uint(As[r+g+8][kk+q  ]);
                a[mt][2] = __float_as_uint(As[r+g  ][kk+q+4]);
                a[mt][3] = __float_as_uint(As[r+g+8][kk+q+4]);
            }
            #pragma unroll
            for (int nt=0; nt<8; nt++){
                uint32_t b0 = __float_as_uint(Ws[kk+q  ][wn+nt*8+g]);
                uint32_t b1 = __float_as_uint(Ws[kk+q+4][wn+nt*8+g]);
                #pragma unroll
                for (int mt=0; mt<2; mt++){
                    asm volatile(
                        "mma.sync.aligned.m16n8k8.row.col.f32.tf32.tf32.f32 "
                        "{%0,%1,%2,%3}, {%4,%5,%6,%7}, {%8,%9}, {%0,%1,%2,%3};"
                        : "+f"(acc[mt][nt][0]), "+f"(acc[mt][nt][1]),
                          "+f"(acc[mt][nt][2]), "+f"(acc[mt][nt][3])
                        : "r"(a[mt][0]), "r"(a[mt][1]), "r"(a[mt][2]), "r"(a[mt][3]),
                          "r"(b0), "r"(b1));
                }
            }
        }
        __syncthreads();
    }
    #pragma unroll
    for (int mt=0; mt<2; mt++){
        int r0 = m0 + wm + mt*16 + g;
        #pragma unroll
        for (int nt=0; nt<8; nt++){
            int c = wn + nt*8 + q*2;
            if (r0 < M)
                *(__half2*)&Out[(size_t)r0*128 + c] =
                    __floats2half2_rn(acc[mt][nt][0], acc[mt][nt][1]);
            if (r0 + 8 < M)
                *(__half2*)&Out[(size_t)(r0+8)*128 + c] =
                    __floats2half2_rn(acc[mt][nt][2], acc[mt][nt][3]);
        }
    }
}

// ---------------- small-tile fp32 GEMM (MLP head) ----------------
__global__ __launch_bounds__(256) void k_gemm_s(
    const float* __restrict__ A, const float* __restrict__ Bw,
    const float* __restrict__ bias, float* __restrict__ Out,
    int M, int Nn, int K, int relu)
{
    __shared__ float As[16][33];
    __shared__ float Bs[16][68];
    int tid = threadIdx.x;
    int m0 = blockIdx.x*32, n0 = blockIdx.y*64;
    int ty = tid >> 4;
    int tx = tid & 15;
    float acc[2][4];
    #pragma unroll
    for (int r=0;r<2;r++)
        #pragma unroll
        for (int c=0;c<4;c++) acc[r][c] = 0.f;

    for (int k0=0; k0<K; k0+=16){
        {
            int idx = tid * 2;
            int row = idx >> 4;
            int kk  = idx & 15;
            float2 v = *(const float2*)&A[(size_t)(m0+row)*K + k0 + kk];
            As[kk  ][row] = v.x;
            As[kk+1][row] = v.y;
        }
        {
            int kk = tid >> 4;
            int c  = (tid & 15) * 4;
            float4 v = *(const float4*)&Bw[(size_t)(k0+kk)*Nn + n0 + c];
            *(float4*)&Bs[kk][c] = v;
        }
        __syncthreads();
        #pragma unroll
        for (int kk=0; kk<16; kk++){
            float a0 = As[kk][ty];
            float a1 = As[kk][ty+16];
            float4 bv = *(float4*)&Bs[kk][tx*4];
            acc[0][0] = fmaf(a0, bv.x, acc[0][0]);
            acc[0][1] = fmaf(a0, bv.y, acc[0][1]);
            acc[0][2] = fmaf(a0, bv.z, acc[0][2]);
            acc[0][3] = fmaf(a0, bv.w, acc[0][3]);
            acc[1][0] = fmaf(a1, bv.x, acc[1][0]);
            acc[1][1] = fmaf(a1, bv.y, acc[1][1]);
            acc[1][2] = fmaf(a1, bv.z, acc[1][2]);
            acc[1][3] = fmaf(a1, bv.w, acc[1][3]);
        }
        __syncthreads();
    }
    #pragma unroll
    for (int r=0;r<2;r++){
        int row = m0 + ty + r*16;
        int cc  = n0 + tx*4;
        float4 o = make_float4(acc[r][0], acc[r][1], acc[r][2], acc[r][3]);
        o.x += bias[cc]; o.y += bias[cc+1]; o.z += bias[cc+2]; o.w += bias[cc+3];
        if (relu){ o.x=fmaxf(o.x,0.f); o.y=fmaxf(o.y,0.f); o.z=fmaxf(o.z,0.f); o.w=fmaxf(o.w,0.f); }
        *(float4*)&Out[(size_t)row*Nn + cc] = o;
    }
}

// ---------------- GCN aggregation (at machine gather limit) ----------------
__global__ __launch_bounds__(256, 4) void k_gcn_agg(
    const __half* __restrict__ h, const float* __restrict__ bias, int nmax)
{
    __shared__ float4 rsum[8][32];
    __shared__ float4 rsq [8][32];
    int tid  = threadIdx.x;
    int warp = tid >> 5, lane = tid & 31;
    int node = blockIdx.x*8 + warp;
    float4 acc = make_float4(0.f,0.f,0.f,0.f);
    if (node < nmax){
        int p0 = g_rowptr[node], p1 = g_rowptr[node+1];
        const __half* hb = h + lane*4;
        int p = p0;
        for (; p + 8 <= p1; p += 8){
            int ss[8]; float ww[8];
            #pragma unroll
            for (int j=0;j<8;j++){ ss[j] = g_col[p+j]; ww[j] = g_enorm[p+j]; }
            float4 vv[8];
            #pragma unroll
            for (int j=0;j<8;j++) vv[j] = ldh4(hb + (size_t)ss[j]*CH);
            #pragma unroll
            for (int j=0;j<8;j++){
                acc.x = fmaf(ww[j], vv[j].x, acc.x);
                acc.y = fmaf(ww[j], vv[j].y, acc.y);
                acc.z = fmaf(ww[j], vv[j].z, acc.z);
                acc.w = fmaf(ww[j], vv[j].w, acc.w);
            }
        }
        for (; p < p1; p++){
            int s = g_col[p];
            float w = g_enorm[p];
            float4 v = ldh4(hb + (size_t)s*CH);
            acc.x = fmaf(w, v.x, acc.x);
            acc.y = fmaf(w, v.y, acc.y);
            acc.z = fmaf(w, v.z, acc.z);
            acc.w = fmaf(w, v.w, acc.w);
        }
        float4 bb = ((const float4*)bias)[lane];
        acc.x += bb.x; acc.y += bb.y; acc.z += bb.z; acc.w += bb.w;
        *((float4*)g_agg + (size_t)node*32 + lane) = acc;
        rsum[warp][lane] = acc;
        rsq [warp][lane] = make_float4(acc.x*acc.x, acc.y*acc.y, acc.z*acc.z, acc.w*acc.w);
    } else {
        rsum[warp][lane] = make_float4(0.f,0.f,0.f,0.f);
        rsq [warp][lane] = make_float4(0.f,0.f,0.f,0.f);
    }
    __syncthreads();
    if (tid < CH){
        const float* ps = (const float*)rsum;
        const float* pq = (const float*)rsq;
        float s = 0.f, q = 0.f;
        #pragma unroll
        for (int w=0; w<8; w++){ s += ps[w*128 + tid]; q += pq[w*128 + tid]; }
        atomicAdd(&g_bnstat[tid],      s);
        atomicAdd(&g_bnstat[CH + tid], q);
    }
}

// ---------------- BN finalize (self-zeroing) ----------------
__global__ void k_bnfin(const float* __restrict__ g, const float* __restrict__ be){
    int c = threadIdx.x;
    float mean = g_bnstat[c] * (1.f/NN);
    float var  = g_bnstat[CH+c] * (1.f/NN) - mean*mean;
    float sc   = g[c] * rsqrtf(var + 1e-5f);
    g_bnscale[c] = sc;
    g_bnshift[c] = be[c] - mean*sc;
    g_bnstat[c] = 0.f;
    g_bnstat[CH + c] = 0.f;
}

// ---------------- GAT: per-node attention scalars (fp16 h) ----------------
__global__ void k_esed(const __half* __restrict__ h, const float* __restrict__ as,
                       const float* __restrict__ ad)
{
    int gt = blockIdx.x*blockDim.x + threadIdx.x;
    int node = gt >> 5, lane = gt & 31;
    if (node >= NN) return;
    float4 v = ldh4(h + (size_t)node*CH + lane*4);
    float4 a = ((const float4*)as)[lane];
    float4 d = ((const float4*)ad)[lane];
    float es = v.x*a.x + v.y*a.y + v.z*a.z + v.w*a.w;
    float ed = v.x*d.x + v.y*d.y + v.z*d.z + v.w*d.w;
    es = warp_sum(es); ed = warp_sum(ed);
    if (lane == 0){ g_es[node] = es; g_ed[node] = ed; }
}

// ---------------- GAT aggregation ----------------
__global__ __launch_bounds__(256, 4) void k_gat_agg(
    const __half* __restrict__ h, const float* __restrict__ bias)
{
    __shared__ float4 rsum[8][32];
    __shared__ float4 rsq [8][32];
    int tid = threadIdx.x;
    int warp = tid >> 5, lane = tid & 31;
    int node = blockIdx.x*8 + warp;
    float4 acc = make_float4(0.f,0.f,0.f,0.f);
    if (node < NN){
        int p0 = g_rowptr[node], p1 = g_rowptr[node+1];
        float edi = g_ed[node];
        float m = -1e30f;
        for (int p = p0 + lane; p < p1; p += 32){
            float e = g_es[g_col[p]] + edi;
            e = (e > 0.f) ? e : 0.2f*e;
            m = fmaxf(m, e);
        }
        m = warp_max(m);
        float s = 0.f;
        int p = p0;
        for (; p + 4 <= p1; p += 4){
            int ss[4];
            #pragma unroll
            for (int j=0;j<4;j++) ss[j] = g_col[p+j];
            float ex[4];
            #pragma unroll
            for (int j=0;j<4;j++){
                float e = g_es[ss[j]] + edi;
                e = (e > 0.f) ? e : 0.2f*e;
                ex[j] = expf(e - m);
            }
            float4 vv[4];
            #pragma unroll
            for (int j=0;j<4;j++) vv[j] = ldh4(h + (size_t)ss[j]*CH + lane*4);
            #pragma unroll
            for (int j=0;j<4;j++){
                s += ex[j];
                acc.x = fmaf(ex[j], vv[j].x, acc.x);
                acc.y = fmaf(ex[j], vv[j].y, acc.y);
                acc.z = fmaf(ex[j], vv[j].z, acc.z);
                acc.w = fmaf(ex[j], vv[j].w, acc.w);
            }
        }
        for (; p < p1; p++){
            int sc = g_col[p];
            float e = g_es[sc] + edi;
            e = (e > 0.f) ? e : 0.2f*e;
            float exv = expf(e - m);
            s += exv;
            float4 v = ldh4(h + (size_t)sc*CH + lane*4);
            acc.x = fmaf(exv, v.x, acc.x);
            acc.y = fmaf(exv, v.y, acc.y);
            acc.z = fmaf(exv, v.z, acc.z);
            acc.w = fmaf(exv, v.w, acc.w);
        }
        float inv = 1.f / (s + 1e-16f);
        float4 bb = ((const float4*)bias)[lane];
        acc.x = acc.x*inv + bb.x;
        acc.y = acc.y*inv + bb.y;
        acc.z = acc.z*inv + bb.z;
        acc.w = acc.w*inv + bb.w;
        *((float4*)g_agg + (size_t)node*32 + lane) = acc;
        rsum[warp][lane] = acc;
        rsq [warp][lane] = make_float4(acc.x*acc.x, acc.y*acc.y, acc.z*acc.z, acc.w*acc.w);
    } else {
        rsum[warp][lane] = make_float4(0.f,0.f,0.f,0.f);
        rsq [warp][lane] = make_float4(0.f,0.f,0.f,0.f);
    }
    __syncthreads();
    if (tid < CH){
        const float* ps = (const float*)rsum;
        const float* pq = (const float*)rsq;
        float s = 0.f, q = 0.f;
        #pragma unroll
        for (int w=0; w<8; w++){ s += ps[w*128 + tid]; q += pq[w*128 + tid]; }
        atomicAdd(&g_bnstat[tid],      s);
        atomicAdd(&g_bnstat[CH + tid], q);
    }
}

// ---------------- pooling (BN apply + residual + run-length sums + counts fused) ----------------
__global__ void k_pool_bn(const int* __restrict__ batch,
                          const float* __restrict__ agg, const float* __restrict__ res)
{
    int gw   = (blockIdx.x*blockDim.x + threadIdx.x) >> 5;
    int lane = threadIdx.x & 31;
    int n0 = gw * 16;
    if (n0 >= NN) return;
    int nend = min(n0 + 16, NN);
    float4 sc = ((const float4*)g_bnscale)[lane];
    float4 sh = ((const float4*)g_bnshift)[lane];
    int curb = batch[n0];
    int runcnt = 0;
    float4 acc = make_float4(0.f,0.f,0.f,0.f);
    for (int n=n0; n<nend; n++){
        int b = batch[n];
        if (b != curb){
            int base = curb*CH + lane*4;
            atomicAdd(&g_pool[base+0], acc.x);
            atomicAdd(&g_pool[base+1], acc.y);
            atomicAdd(&g_pool[base+2], acc.z);
            atomicAdd(&g_pool[base+3], acc.w);
            if (lane == 0) atomicAdd(&g_cnt[curb], runcnt);
            acc = make_float4(0.f,0.f,0.f,0.f);
            runcnt = 0;
            curb = b;
        }
        size_t off = (size_t)n*32 + lane;
        float4 a = ((const float4*)agg)[off];
        float4 r = ((const float4*)res)[off];
        acc.x += fmaxf(fmaf(a.x, sc.x, sh.x), 0.f) + r.x;
        acc.y += fmaxf(fmaf(a.y, sc.y, sh.y), 0.f) + r.y;
        acc.z += fmaxf(fmaf(a.z, sc.z, sh.z), 0.f) + r.z;
        acc.w += fmaxf(fmaf(a.w, sc.w, sh.w), 0.f) + r.w;
        runcnt++;
    }
    int base = curb*CH + lane*4;
    atomicAdd(&g_pool[base+0], acc.x);
    atomicAdd(&g_pool[base+1], acc.y);
    atomicAdd(&g_pool[base+2], acc.z);
    atomicAdd(&g_pool[base+3], acc.w);
    if (lane == 0) atomicAdd(&g_cnt[curb], runcnt);
}
__global__ void k_pooldiv(){
    int b = blockIdx.x, c = threadIdx.x;
    float inv = 1.f / fmaxf((float)g_cnt[b], 1.f);
    g_pooled[b*CH + c] = g_pool[b*CH + c] * inv;
    g_pool[b*CH + c] = 0.f;
    if (c == 0) g_cnt[b] = 0;
}

// ---------------- launch ----------------
extern "C" void kernel_launch(void* const* d_in, const int* in_sizes, int n_in,
                              void* d_out, int out_size)
{
    const float* x     = (const float*)d_in[0];
    const int*   ei    = (const int*)  d_in[1];
    const int*   batch = (const int*)  d_in[2];
    const float* W1  = (const float*)d_in[3];
    const float* b1  = (const float*)d_in[4];
    const float* gm1 = (const float*)d_in[5];
    const float* be1 = (const float*)d_in[6];
    const float* W2  = (const float*)d_in[7];
    const float* b2  = (const float*)d_in[8];
    const float* gm2 = (const float*)d_in[9];
    const float* be2 = (const float*)d_in[10];
    const float* W3  = (const float*)d_in[11];
    const float* b3  = (const float*)d_in[12];
    const float* gm3 = (const float*)d_in[13];
    const float* be3 = (const float*)d_in[14];
    const float* Wa   = (const float*)d_in[15];
    const float* asrc = (const float*)d_in[16];
    const float* adst = (const float*)d_in[17];
    const float* ba   = (const float*)d_in[18];
    const float* ga   = (const float*)d_in[19];
    const float* bea  = (const float*)d_in[20];
    const float* Wh1 = (const float*)d_in[21];
    const float* bh1 = (const float*)d_in[22];
    const float* Wm0 = (const float*)d_in[23];
    const float* bm0 = (const float*)d_in[24];
    const float* Wm1 = (const float*)d_in[25];
    const float* bm1 = (const float*)d_in[26];
    const float* Wo  = (const float*)d_in[27];
    const float* bo  = (const float*)d_in[28];

    __half *ph;
    float *px, *pagg, *ppooled, *py1, *py2;
    cudaGetSymbolAddress((void**)&ph,      g_h16);
    cudaGetSymbolAddress((void**)&px,      g_x);
    cudaGetSymbolAddress((void**)&pagg,    g_agg);
    cudaGetSymbolAddress((void**)&ppooled, g_pooled);
    cudaGetSymbolAddress((void**)&py1,     g_y1);
    cudaGetSymbolAddress((void**)&py2,     g_y2);

    const int T = 256;
    const int TC_GX  = (NN + 127) / 128;
    const int AGG_B  = (NN + 7) / 8;

    // ---- CSR build ----
    k_init_deg <<<(NN+T-1)/T, T>>>();
    k_count_deg<<<(EE+T-1)/T, T>>>(ei);
    k_dinv     <<<(NN+T-1)/T, T>>>();
    k_scan1    <<<NB_SCAN, 1024>>>();
    k_scan2    <<<1, 32>>>();
    k_scan3    <<<(NN+T-1)/T, T>>>();
    k_scatter  <<<(ELL+T-1)/T, T>>>(ei);

    // ---- GCN layer 1 ----
    k_gemm_tc<<<TC_GX, 256>>>(x, W1, ph, NN);
    k_gcn_agg<<<AGG_B, 256>>>(ph, b1, NN);
    k_bnfin<<<1, CH>>>(gm1, be1);

    // ---- layer 2: fused apply(layer1) + GEMM ----
    k_gemm_tc_bn<<<TC_GX, 256>>>(pagg, x, px, W2, ph, NN);
    k_gcn_agg<<<AGG_B, 256>>>(ph, b2, NN);
    k_bnfin<<<1, CH>>>(gm2, be2);

    // ---- layer 3: fused apply(layer2) + GEMM ----
    k_gemm_tc_bn<<<TC_GX, 256>>>(pagg, px, px, W3, ph, NN);
    k_gcn_agg<<<AGG_B, 256>>>(ph, b3, NN);
    k_bnfin<<<1, CH>>>(gm3, be3);

    // ---- GAT layer: fused apply(layer3) + GEMM ----
    k_gemm_tc_bn<<<TC_GX, 256>>>(pagg, px, px, Wa, ph, NN);
    k_esed<<<(NN*32+T-1)/T, T>>>(ph, asrc, adst);
    k_gat_agg<<<AGG_B, 256>>>(ph, ba);
    k_bnfin<<<1, CH>>>(ga, bea);

    // ---- global mean pool (fused BN apply + counts) ----
    {
        int warps = (NN + 15) / 16;
        int blocks = (warps*32 + T - 1) / T;
        k_pool_bn<<<blocks, T>>>(batch, pagg, px);
    }
    k_pooldiv<<<BG, CH>>>();

    // ---- MLP head ----
    k_gemm_s<<<dim3(BG/32, NHID/64), 256>>>(ppooled, Wh1, bh1, py1, BG, NHID, CH,   1);
    k_gemm_s<<<dim3(BG/32, NHID/64), 256>>>(py1,     Wm0, bm0, py2, BG, NHID, NHID, 1);
    k_gemm_s<<<dim3(BG/32, NHID/64), 256>>>(py2,     Wm1, bm1, py1, BG, NHID, NHID, 1);
    k_gemm_s<<<dim3(BG/32, NOUT/64), 256>>>(py1,     Wo,  bo,  (float*)d_out, BG, NOUT, NHID, 0);
}